// round 3
// baseline (speedup 1.0000x reference)
#include <cuda_runtime.h>
#include <math.h>

#define C 128
#define BMAX 4096
#define NMAX 500000

// ---------------- scratch (device globals; 16B-aligned for float4 access) --
__device__ __align__(16) float g_X[BMAX * 2 * C];       // [B, 2C] = [h | r]
__device__ __align__(16) float g_gates[BMAX * 4 * C];   // [B, 4C]
__device__ __align__(16) float g_c[BMAX * C];           // cell state
__device__ __align__(16) float g_e[NMAX];               // per-node logits
__device__ __align__(16) float g_Wc[4 * C * 2 * C];     // combined weight [4C, 2C]
__device__ __align__(16) float g_bias[4 * C];           // b_ih + b_hh
__device__ int   g_seg[BMAX + 1];                       // segment offsets

__device__ __forceinline__ float sigf(float x) { return 1.0f / (1.0f + __expf(-x)); }

// ---------------- prep: combined weights / bias ----------------------------
__global__ void prep_kernel(const float* __restrict__ W_ih,
                            const float* __restrict__ W_hh,
                            const float* __restrict__ b_ih,
                            const float* __restrict__ b_hh) {
    int idx = blockIdx.x * blockDim.x + threadIdx.x;   // over 4C * 2C
    if (idx < 4 * C * 2 * C) {
        int n = idx >> 8;          // row in [0, 4C)   (2C == 256)
        int kk = idx & (2 * C - 1);
        float w = W_ih[n * 2 * C + kk];
        if (kk < C) w += W_hh[n * C + kk];   // fold W_hh (x[:, :C] == h0)
        g_Wc[idx] = w;
    }
    if (idx < 4 * C) g_bias[idx] = b_ih[idx] + b_hh[idx];
}

// ---------------- segment offsets from sorted batch ------------------------
// batch buffer is int32 per harness dtype narrowing (jax x64 disabled).
// Robustness probe: if the data were really int64 (LE), the int32 word at
// index N-1 is a high word == 0; for int32 sorted data it's ~B-1 != 0.
__device__ __forceinline__ int bload(const int* p, int i, int is64) {
    return is64 ? p[2 * i] : p[i];
}

__global__ void seg_kernel(const int* __restrict__ batch, int N, int B) {
    int i = blockIdx.x * blockDim.x + threadIdx.x;
    if (i > N) return;
    const int is64 = (batch[N - 1] == 0);
    if (i == 0) {
        int b0 = bload(batch, 0, is64);
        for (int b = 0; b <= b0; b++) g_seg[b] = 0;
    } else if (i == N) {
        int bl = bload(batch, N - 1, is64);
        for (int b = bl + 1; b <= B; b++) g_seg[b] = N;
    } else {
        int bc = bload(batch, i, is64), bp = bload(batch, i - 1, is64);
        for (int b = bp + 1; b <= bc; b++) g_seg[b] = i;
    }
}

// ---------------- SGEMM: gates = A[B,K] @ W[4C,K]^T + bias -----------------
// BM=128, BN=128, BK=16, 256 threads, 8x8 per-thread tile.
template <int K>
__global__ __launch_bounds__(256)
void gemm_gates(const float* __restrict__ Aext, const float* __restrict__ Wext) {
    const float* A = (K == C) ? Aext : g_X;
    const float* W = (K == C) ? Wext : g_Wc;

    __shared__ __align__(16) float As[16][132];
    __shared__ __align__(16) float Bs[16][132];

    const int bn = blockIdx.x;     // N tile (0..3)
    const int bm = blockIdx.y;     // M tile
    const int tid = threadIdx.x;
    const int tx = tid & 15;
    const int ty = tid >> 4;

    float acc[8][8];
#pragma unroll
    for (int i = 0; i < 8; i++)
#pragma unroll
        for (int j = 0; j < 8; j++) acc[i][j] = 0.0f;

    const float* Aptr = A + (size_t)bm * 128 * K;
    const float* Bptr = W + (size_t)bn * 128 * K;

    for (int k0 = 0; k0 < K; k0 += 16) {
#pragma unroll
        for (int f = tid; f < 512; f += 256) {
            int row = f >> 2, c4 = f & 3;
            float4 a = *(const float4*)(Aptr + (size_t)row * K + k0 + c4 * 4);
            As[c4 * 4 + 0][row] = a.x; As[c4 * 4 + 1][row] = a.y;
            As[c4 * 4 + 2][row] = a.z; As[c4 * 4 + 3][row] = a.w;
        }
#pragma unroll
        for (int f = tid; f < 512; f += 256) {
            int row = f >> 2, c4 = f & 3;
            float4 b = *(const float4*)(Bptr + (size_t)row * K + k0 + c4 * 4);
            Bs[c4 * 4 + 0][row] = b.x; Bs[c4 * 4 + 1][row] = b.y;
            Bs[c4 * 4 + 2][row] = b.z; Bs[c4 * 4 + 3][row] = b.w;
        }
        __syncthreads();
#pragma unroll
        for (int kk = 0; kk < 16; kk++) {
            float ra[8], rb[8];
#pragma unroll
            for (int i = 0; i < 8; i++) ra[i] = As[kk][ty * 8 + i];
#pragma unroll
            for (int j = 0; j < 8; j++) rb[j] = Bs[kk][tx * 8 + j];
#pragma unroll
            for (int i = 0; i < 8; i++)
#pragma unroll
                for (int j = 0; j < 8; j++)
                    acc[i][j] = fmaf(ra[i], rb[j], acc[i][j]);
        }
        __syncthreads();
    }

    int grow = bm * 128 + ty * 8;
    int gcol = bn * 128 + tx * 8;
#pragma unroll
    for (int i = 0; i < 8; i++) {
#pragma unroll
        for (int j = 0; j < 8; j++) {
            g_gates[(size_t)(grow + i) * (4 * C) + gcol + j] = acc[i][j] + g_bias[gcol + j];
        }
    }
}

// ---------------- elementwise LSTM cell update ------------------------------
__global__ void lstm_cell(const float* __restrict__ h_ext, int first, int B) {
    int idx = blockIdx.x * blockDim.x + threadIdx.x;
    if (idx >= B * C) return;
    int b = idx >> 7, c = idx & (C - 1);
    const float* g = g_gates + (size_t)b * 4 * C;
    float ci = first ? h_ext[idx] : g_c[idx];
    float gi = g[c], gf = g[C + c], gg = g[2 * C + c], go = g[3 * C + c];
    float cn = sigf(gf) * ci + sigf(gi) * tanhf(gg);
    g_c[idx] = cn;
    g_X[(size_t)b * 2 * C + c] = sigf(go) * tanhf(cn);  // h_new == q
}

// ---------------- segment attention: one block per segment -----------------
// Pass 1: e_i = k_i . q, segment max.  Pass 2: softmax-weighted sum of v.
__global__ __launch_bounds__(256)
void attn_kernel(const float* __restrict__ kmat, const float* __restrict__ vmat,
                 float* __restrict__ out, int iter) {
    int b = blockIdx.x;
    int tid = threadIdx.x;
    int lane = tid & 31;
    int w = tid >> 5;                       // 8 warps
    int start = g_seg[b], end = g_seg[b + 1];

    float4 q4 = *(const float4*)(g_X + (size_t)b * 2 * C + lane * 4);

    __shared__ float smax[8];
    __shared__ float ssum[8];
    __shared__ __align__(16) float sr[8][C];

    // ---- pass 1: logits + max (unroll 2 for MLP) ----
    float wmax = -INFINITY;
    int node = start + w;
    for (; node + 8 < end; node += 16) {
        float4 ka = *(const float4*)(kmat + (size_t)node * C + lane * 4);
        float4 kb = *(const float4*)(kmat + (size_t)(node + 8) * C + lane * 4);
        float da = ka.x * q4.x + ka.y * q4.y + ka.z * q4.z + ka.w * q4.w;
        float db = kb.x * q4.x + kb.y * q4.y + kb.z * q4.z + kb.w * q4.w;
#pragma unroll
        for (int off = 16; off > 0; off >>= 1) {
            da += __shfl_xor_sync(0xFFFFFFFFu, da, off);
            db += __shfl_xor_sync(0xFFFFFFFFu, db, off);
        }
        if (lane == 0) { g_e[node] = da; g_e[node + 8] = db; }
        wmax = fmaxf(wmax, fmaxf(da, db));
    }
    for (; node < end; node += 8) {
        float4 ka = *(const float4*)(kmat + (size_t)node * C + lane * 4);
        float da = ka.x * q4.x + ka.y * q4.y + ka.z * q4.z + ka.w * q4.w;
#pragma unroll
        for (int off = 16; off > 0; off >>= 1)
            da += __shfl_xor_sync(0xFFFFFFFFu, da, off);
        if (lane == 0) g_e[node] = da;
        wmax = fmaxf(wmax, da);
    }
    if (lane == 0) smax[w] = wmax;
    __syncthreads();

    float m = -INFINITY;
#pragma unroll
    for (int i = 0; i < 8; i++) m = fmaxf(m, smax[i]);

    // ---- pass 2: exp + weighted V sum ----
    float s = 0.0f;
    float4 r4 = make_float4(0.f, 0.f, 0.f, 0.f);
    for (node = start + w; node < end; node += 8) {
        float a = __expf(g_e[node] - m);
        float4 v4 = *(const float4*)(vmat + (size_t)node * C + lane * 4);
        s += a;
        r4.x = fmaf(a, v4.x, r4.x); r4.y = fmaf(a, v4.y, r4.y);
        r4.z = fmaf(a, v4.z, r4.z); r4.w = fmaf(a, v4.w, r4.w);
    }
    if (lane == 0) ssum[w] = s;
    *(float4*)(&sr[w][lane * 4]) = r4;
    __syncthreads();

    if (tid < C) {
        float stot = 0.0f, rc = 0.0f;
#pragma unroll
        for (int i = 0; i < 8; i++) { stot += ssum[i]; rc += sr[i][tid]; }
        float val = rc / (stot + 1e-16f);
        g_X[(size_t)b * 2 * C + C + tid] = val;                 // r half for next LSTM
        out[(size_t)b * 4 * C + iter * C + tid] = val;          // readout slot
    }
}

// ---------------- launch ----------------------------------------------------
extern "C" void kernel_launch(void* const* d_in, const int* in_sizes, int n_in,
                              void* d_out, int out_size) {
    const float* k     = (const float*)d_in[0];
    const float* v     = (const float*)d_in[1];
    const float* h     = (const float*)d_in[2];
    const float* W_ih  = (const float*)d_in[3];
    const float* W_hh  = (const float*)d_in[4];
    const float* b_ih  = (const float*)d_in[5];
    const float* b_hh  = (const float*)d_in[6];
    const int*   batch = (const int*)d_in[7];
    float* out = (float*)d_out;

    int N = in_sizes[0] / C;
    int B = in_sizes[2] / C;

    prep_kernel<<<(4 * C * 2 * C + 255) / 256, 256>>>(W_ih, W_hh, b_ih, b_hh);
    seg_kernel<<<(N + 256) / 256, 256>>>(batch, N, B);

    for (int t = 0; t < 4; t++) {
        if (t == 0)
            gemm_gates<C><<<dim3(4, B / 128), 256>>>(h, W_hh);
        else
            gemm_gates<2 * C><<<dim3(4, B / 128), 256>>>(nullptr, nullptr);
        lstm_cell<<<(B * C + 255) / 256, 256>>>(h, t == 0 ? 1 : 0, B);
        attn_kernel<<<B, 256>>>(k, v, out, t);
    }
}